// round 15
// baseline (speedup 1.0000x reference)
#include <cuda_runtime.h>
#include <cstdint>

#define L 8
#define B 128
#define NL 32
#define NP 256
#define N_LIG (B*NL)
#define N_PROT (B*NP)
#define E_PL_G 1024
#define E_LL_G 256
#define F 128
#define H 256
#define OUT 2

#define WEFF_BLOCKS 129   // 128 weff blocks (16 rows each) + 1 beff block
#define AGG_BLOCKS  (L*B) // 1024
#define WEFF_TARGET WEFF_BLOCKS
// total grid = 1153 <= 1184 (8 blocks/SM x 148 SMs) -> single wave

// Scratch (device globals, zero-initialized; protocol restores zeros each call)
__device__ float g_weff_pl[L * F * OUT];   // W_pl[l] @ W_fc[l*H:(l+1)*H]
__device__ float g_weff_ll[L * F * OUT];
__device__ float g_beff[OUT];
__device__ int   g_weff_ready;             // counts finished weff/beff blocks
__device__ float g_logit[B * OUT];         // accumulated logits per graph
__device__ int   g_cnt[B];                 // finished agg blocks per graph
__device__ int   g_done;                   // finished graphs

struct SmemAgg {
    alignas(16) float partial0[8 * F];  // per-warp PL partials
    alignas(16) float partial1[8 * F];  // per-warp LL partials
    unsigned short pack_pl[E_PL_G];     // (dst_local<<8) | src_local
    unsigned short pack_ll[E_LL_G];
    int   cnt_src_p[NP];
    float coeff_p[NP];
    int   cnt_src_l[NL];
    float coeff_l[NL];
    int   cnt_dst_p[NL];
    int   cnt_dst_l[NL];
    float rs_dst_p[NL];
    float rs_dst_l[NL];
};

// Single kernel. Blocks [0,129): weff/beff precompute (retire early, signal via
// g_weff_ready). Blocks [129, 1153): per-(layer,graph) merged two-relation
// aggregation + logit; last block per graph applies beff + sigmoid, writes out.
__global__ __launch_bounds__(256) void fused_kernel(
    const float* __restrict__ feat_lig, const float* __restrict__ feat_prot,
    const int* __restrict__ src_pl, const int* __restrict__ dst_pl,
    const int* __restrict__ src_ll, const int* __restrict__ dst_ll,
    const float* __restrict__ W_pl, const float* __restrict__ W_ll,
    const float* __restrict__ b_pl, const float* __restrict__ b_ll,
    const float* __restrict__ W_fc, const float* __restrict__ b_fc,
    float* __restrict__ out)
{
    const int tid  = threadIdx.x;
    const int warp = tid >> 5, lane = tid & 31;

    if (blockIdx.x < 128) {
        // ---- weff: 16 rows per block, 2 per warp; warp-reduced dot over h ----
        #pragma unroll
        for (int k = 0; k < 2; k++) {
            const int R   = blockIdx.x * 16 + warp * 2 + k;  // 0..2047
            const int rel = R >> 10;           // 0: pl, 1: ll
            const int l   = (R >> 7) & 7;
            const int f   = R & 127;

            const float* W    = rel ? W_ll : W_pl;
            float*       Weff = rel ? g_weff_ll : g_weff_pl;

            const float* wrow = W + ((size_t)l * F + f) * H;
            const float* fc   = W_fc + (size_t)l * H * OUT;

            float a0 = 0.f, a1 = 0.f;
            #pragma unroll
            for (int h = lane; h < H; h += 32) {
                float w = wrow[h];
                a0 += w * fc[h * OUT + 0];
                a1 += w * fc[h * OUT + 1];
            }
            #pragma unroll
            for (int o = 16; o > 0; o >>= 1) {
                a0 += __shfl_xor_sync(0xffffffffu, a0, o);
                a1 += __shfl_xor_sync(0xffffffffu, a1, o);
            }
            if (lane == 0) {
                Weff[((size_t)l * F + f) * OUT + 0] = a0;
                Weff[((size_t)l * F + f) * OUT + 1] = a1;
            }
        }
        __syncthreads();
        if (tid == 0) {
            __threadfence();
            atomicAdd(&g_weff_ready, 1);
        }
        return;
    }
    if (blockIdx.x == 128) {
        // ---- beff = b_fc + sum_j (b_pl+b_ll)[j] * W_fc[j,:] ----
        __shared__ float red0[256], red1[256];
        float a0 = 0.f, a1 = 0.f;
        for (int j = tid; j < L * H; j += 256) {
            float bb = b_pl[j] + b_ll[j];
            a0 += bb * W_fc[j * OUT + 0];
            a1 += bb * W_fc[j * OUT + 1];
        }
        red0[tid] = a0; red1[tid] = a1;
        __syncthreads();
        #pragma unroll
        for (int st = 128; st > 0; st >>= 1) {
            if (tid < st) { red0[tid] += red0[tid + st]; red1[tid] += red1[tid + st]; }
            __syncthreads();
        }
        if (tid == 0) {
            g_beff[0] = red0[0] + b_fc[0];
            g_beff[1] = red1[0] + b_fc[1];
            __threadfence();
            atomicAdd(&g_weff_ready, 1);
        }
        return;
    }

    // ================= aggregation blocks: merged two-relation pass =========
    __shared__ SmemAgg s;
    const int gb = blockIdx.x - WEFF_BLOCKS;
    const int l = gb / B;
    const int b = gb % B;

    const float* fp = feat_prot + ((size_t)l * N_PROT + b * NP) * F;
    const float* fl = feat_lig  + ((size_t)l * N_LIG  + b * NL) * F;

    const int* spl = src_pl + (size_t)l * B * E_PL_G + (size_t)b * E_PL_G;
    const int* dpl = dst_pl + (size_t)l * B * E_PL_G + (size_t)b * E_PL_G;
    const int* sll = src_ll + (size_t)l * B * E_LL_G + (size_t)b * E_LL_G;
    const int* dll = dst_ll + (size_t)l * B * E_LL_G + (size_t)b * E_LL_G;

    const int src_base_p = b * NP;
    const int dst_base   = b * NL;

    // ---- zero all counters ----
    for (int i = tid; i < NP; i += 256) s.cnt_src_p[i] = 0;
    if (tid < NL) {
        s.cnt_src_l[tid] = 0;
        s.cnt_dst_p[tid] = 0;
        s.cnt_dst_l[tid] = 0;
    }
    __syncthreads();

    // ---- single merged edge phase: all loads issued up front (streaming) ----
    {
        // PL: exactly one int4 per thread (256*4 = 1024 edges)
        int4 sv = __ldcs((const int4*)spl + tid);
        int4 dv = __ldcs((const int4*)dpl + tid);
        // LL: one int4 for threads < 64 (64*4 = 256 edges)
        int4 sv2, dv2;
        if (tid < 64) {
            sv2 = __ldcs((const int4*)sll + tid);
            dv2 = __ldcs((const int4*)dll + tid);
        }

        int sl0 = sv.x - src_base_p, sl1 = sv.y - src_base_p,
            sl2 = sv.z - src_base_p, sl3 = sv.w - src_base_p;
        int dl0 = dv.x - dst_base, dl1 = dv.y - dst_base,
            dl2 = dv.z - dst_base, dl3 = dv.w - dst_base;
        const int e = tid * 4;
        s.pack_pl[e + 0] = (unsigned short)((dl0 << 8) | sl0);
        s.pack_pl[e + 1] = (unsigned short)((dl1 << 8) | sl1);
        s.pack_pl[e + 2] = (unsigned short)((dl2 << 8) | sl2);
        s.pack_pl[e + 3] = (unsigned short)((dl3 << 8) | sl3);
        atomicAdd(&s.cnt_src_p[sl0], 1); atomicAdd(&s.cnt_src_p[sl1], 1);
        atomicAdd(&s.cnt_src_p[sl2], 1); atomicAdd(&s.cnt_src_p[sl3], 1);
        atomicAdd(&s.cnt_dst_p[dl0], 1); atomicAdd(&s.cnt_dst_p[dl1], 1);
        atomicAdd(&s.cnt_dst_p[dl2], 1); atomicAdd(&s.cnt_dst_p[dl3], 1);

        if (tid < 64) {
            int a0 = sv2.x - dst_base, a1 = sv2.y - dst_base,
                a2 = sv2.z - dst_base, a3 = sv2.w - dst_base;
            int c0 = dv2.x - dst_base, c1 = dv2.y - dst_base,
                c2 = dv2.z - dst_base, c3 = dv2.w - dst_base;
            s.pack_ll[e + 0] = (unsigned short)((c0 << 8) | a0);
            s.pack_ll[e + 1] = (unsigned short)((c1 << 8) | a1);
            s.pack_ll[e + 2] = (unsigned short)((c2 << 8) | a2);
            s.pack_ll[e + 3] = (unsigned short)((c3 << 8) | a3);
            atomicAdd(&s.cnt_src_l[a0], 1); atomicAdd(&s.cnt_src_l[a1], 1);
            atomicAdd(&s.cnt_src_l[a2], 1); atomicAdd(&s.cnt_src_l[a3], 1);
            atomicAdd(&s.cnt_dst_l[c0], 1); atomicAdd(&s.cnt_dst_l[c1], 1);
            atomicAdd(&s.cnt_dst_l[c2], 1); atomicAdd(&s.cnt_dst_l[c3], 1);
        }
    }
    __syncthreads();

    // ---- rs_dst (both relations) + zero coeffs ----
    if (tid < NL) {
        int cp = s.cnt_dst_p[tid], cl = s.cnt_dst_l[tid];
        s.rs_dst_p[tid] = rsqrtf((float)(cp > 0 ? cp : 1));
        s.rs_dst_l[tid] = rsqrtf((float)(cl > 0 ? cl : 1));
        s.coeff_l[tid]  = 0.f;
    }
    for (int i = tid; i < NP; i += 256) s.coeff_p[i] = 0.f;
    __syncthreads();

    // ---- coefficient accumulation (both relations in one round) ----
    {
        const int e = tid * 4;
        #pragma unroll
        for (int k = 0; k < 4; k++) {
            unsigned short p = s.pack_pl[e + k];
            atomicAdd(&s.coeff_p[p & 255], s.rs_dst_p[p >> 8]);
        }
        if (tid < E_LL_G) {
            unsigned short p = s.pack_ll[tid];
            atomicAdd(&s.coeff_l[p & 255], s.rs_dst_l[p >> 8]);
        }
    }
    __syncthreads();

    // ---- fold rs_src and 1/NL mean ----
    for (int i = tid; i < NP; i += 256) {
        int c = s.cnt_src_p[i];
        s.coeff_p[i] *= rsqrtf((float)(c > 0 ? c : 1)) * (1.0f / (float)NL);
    }
    if (tid < NL) {
        int c = s.cnt_src_l[tid];
        s.coeff_l[tid] *= rsqrtf((float)(c > 0 ? c : 1)) * (1.0f / (float)NL);
    }
    __syncthreads();

    // ---- single streaming phase: warp w owns 32 protein rows + 4 ligand rows
    // feature loads use .cs (evict-first); rows with coeff==0 (~1.8%) skipped
    // (warp-uniform branch: coeff is per-row, identical across all 32 lanes)
    {
        float4 pp = make_float4(0.f, 0.f, 0.f, 0.f);
        float4 pl = make_float4(0.f, 0.f, 0.f, 0.f);
        const int rp0 = warp * 32;
        #pragma unroll 8
        for (int r = rp0; r < rp0 + 32; r++) {
            float c = s.coeff_p[r];
            if (c != 0.f) {
                float4 v = __ldcs((const float4*)(fp + (size_t)r * F) + lane);
                pp.x += c * v.x; pp.y += c * v.y; pp.z += c * v.z; pp.w += c * v.w;
            }
        }
        const int rl0 = warp * 4;
        #pragma unroll
        for (int r = rl0; r < rl0 + 4; r++) {
            float c = s.coeff_l[r];
            float4 v = __ldcs((const float4*)(fl + (size_t)r * F) + lane);
            pl.x += c * v.x; pl.y += c * v.y; pl.z += c * v.z; pl.w += c * v.w;
        }
        ((float4*)(s.partial0 + warp * F))[lane] = pp;
        ((float4*)(s.partial1 + warp * F))[lane] = pl;
    }
    __syncthreads();

    // ---- wait for weff (done ~2us into the kernel; effectively free) ----
    if (tid == 0) {
        while (atomicCAS(&g_weff_ready, WEFF_TARGET, WEFF_TARGET) != WEFF_TARGET) {}
    }
    __syncthreads();

    // ---- reduce partials + dot with weff -> logit contribution ----
    float a0 = 0.f, a1 = 0.f;
    if (tid < F) {
        float p0 = 0.f, p1 = 0.f;
        #pragma unroll
        for (int w = 0; w < 8; w++) {
            p0 += s.partial0[w * F + tid];
            p1 += s.partial1[w * F + tid];
        }
        const int wi = (l * F + tid) * OUT;
        a0 = p0 * g_weff_pl[wi + 0] + p1 * g_weff_ll[wi + 0];
        a1 = p0 * g_weff_pl[wi + 1] + p1 * g_weff_ll[wi + 1];
    }
    #pragma unroll
    for (int o = 16; o > 0; o >>= 1) {
        a0 += __shfl_xor_sync(0xffffffffu, a0, o);
        a1 += __shfl_xor_sync(0xffffffffu, a1, o);
    }
    __shared__ float s0[8], s1[8];
    if (lane == 0) { s0[warp] = a0; s1[warp] = a1; }
    __syncthreads();

    if (tid == 0) {
        float t0 = s0[0] + s0[1] + s0[2] + s0[3];  // warps 4..7 had tid>=128 -> 0
        float t1 = s1[0] + s1[1] + s1[2] + s1[3];
        atomicAdd(&g_logit[b * OUT + 0], t0);
        atomicAdd(&g_logit[b * OUT + 1], t1);
        __threadfence();
        int old = atomicAdd(&g_cnt[b], 1);
        if (old == L - 1) {
            float v0 = atomicAdd(&g_logit[b * OUT + 0], 0.f) + g_beff[0];
            float v1 = atomicAdd(&g_logit[b * OUT + 1], 0.f) + g_beff[1];
            out[b * OUT + 0] = 1.0f / (1.0f + expf(-v0));
            out[b * OUT + 1] = 1.0f / (1.0f + expf(-v1));
            // restore zeros for the next replay
            g_logit[b * OUT + 0] = 0.f;
            g_logit[b * OUT + 1] = 0.f;
            g_cnt[b] = 0;
            __threadfence();
            int d = atomicAdd(&g_done, 1);
            if (d == B - 1) { g_done = 0; g_weff_ready = 0; __threadfence(); }
        }
    }
}

extern "C" void kernel_launch(void* const* d_in, const int* in_sizes, int n_in,
                              void* d_out, int out_size)
{
    const float* feat_lig  = (const float*)d_in[0];
    const float* feat_prot = (const float*)d_in[1];
    const int*   src_pl    = (const int*)  d_in[2];
    const int*   dst_pl    = (const int*)  d_in[3];
    const int*   src_ll    = (const int*)  d_in[4];
    const int*   dst_ll    = (const int*)  d_in[5];
    const float* W_pl      = (const float*)d_in[6];
    const float* b_pl      = (const float*)d_in[7];
    const float* W_ll      = (const float*)d_in[8];
    const float* b_ll      = (const float*)d_in[9];
    const float* W_fc      = (const float*)d_in[10];
    const float* b_fc      = (const float*)d_in[11];
    float* out = (float*)d_out;

    fused_kernel<<<WEFF_BLOCKS + AGG_BLOCKS, 256>>>(
        feat_lig, feat_prot, src_pl, dst_pl, src_ll, dst_ll,
        W_pl, W_ll, b_pl, b_ll, W_fc, b_fc, out);
}

// round 16
// speedup vs baseline: 1.0471x; 1.0471x over previous
#include <cuda_runtime.h>
#include <cstdint>

#define L 8
#define B 128
#define NL 32
#define NP 256
#define N_LIG (B*NL)
#define N_PROT (B*NP)
#define E_PL_G 1024
#define E_LL_G 256
#define F 128
#define H 256
#define OUT 2

#define WEFF_BLOCKS 129   // 128 weff blocks (16 rows each) + 1 beff block
#define AGG_BLOCKS  (L*B) // 1024
#define WEFF_TARGET WEFF_BLOCKS
// total grid = 1153 <= 1184 (8 blocks/SM x 148 SMs) -> single wave

// Scratch (device globals, zero-initialized; protocol restores zeros each call)
__device__ float g_weff_pl[L * F * OUT];   // W_pl[l] @ W_fc[l*H:(l+1)*H]
__device__ float g_weff_ll[L * F * OUT];
__device__ float g_beff[OUT];
__device__ int   g_weff_ready;             // counts finished weff/beff blocks
__device__ float g_logit[B * OUT];         // accumulated logits per graph
__device__ int   g_cnt[B];                 // finished agg blocks per graph
__device__ int   g_done;                   // finished graphs

struct SmemAgg {
    alignas(16) float partial0[8 * F];  // per-warp PL partials
    alignas(16) float partial1[8 * F];  // per-warp LL partials
    unsigned short pack_pl[E_PL_G];     // (dst_local<<8) | src_local
    unsigned short pack_ll[E_LL_G];
    int   cnt_src_p[NP];
    float coeff_p[NP];
    int   cnt_src_l[NL];
    float coeff_l[NL];
    int   cnt_dst_p[NL];
    int   cnt_dst_l[NL];
    float rs_dst_p[NL];
    float rs_dst_l[NL];
};

// Single kernel. Blocks [0,129): weff/beff precompute (retire early, signal via
// g_weff_ready). Blocks [129, 1153): per-(layer,graph) merged two-relation
// aggregation + logit; last block per graph applies beff + sigmoid, writes out.
__global__ __launch_bounds__(256) void fused_kernel(
    const float* __restrict__ feat_lig, const float* __restrict__ feat_prot,
    const int* __restrict__ src_pl, const int* __restrict__ dst_pl,
    const int* __restrict__ src_ll, const int* __restrict__ dst_ll,
    const float* __restrict__ W_pl, const float* __restrict__ W_ll,
    const float* __restrict__ b_pl, const float* __restrict__ b_ll,
    const float* __restrict__ W_fc, const float* __restrict__ b_fc,
    float* __restrict__ out)
{
    const int tid  = threadIdx.x;
    const int warp = tid >> 5, lane = tid & 31;

    if (blockIdx.x < 128) {
        // ---- weff: 16 rows per block, 2 per warp; warp-reduced dot over h ----
        #pragma unroll
        for (int k = 0; k < 2; k++) {
            const int R   = blockIdx.x * 16 + warp * 2 + k;  // 0..2047
            const int rel = R >> 10;           // 0: pl, 1: ll
            const int l   = (R >> 7) & 7;
            const int f   = R & 127;

            const float* W    = rel ? W_ll : W_pl;
            float*       Weff = rel ? g_weff_ll : g_weff_pl;

            const float* wrow = W + ((size_t)l * F + f) * H;
            const float* fc   = W_fc + (size_t)l * H * OUT;

            float a0 = 0.f, a1 = 0.f;
            #pragma unroll
            for (int h = lane; h < H; h += 32) {
                float w = wrow[h];
                a0 += w * fc[h * OUT + 0];
                a1 += w * fc[h * OUT + 1];
            }
            #pragma unroll
            for (int o = 16; o > 0; o >>= 1) {
                a0 += __shfl_xor_sync(0xffffffffu, a0, o);
                a1 += __shfl_xor_sync(0xffffffffu, a1, o);
            }
            if (lane == 0) {
                Weff[((size_t)l * F + f) * OUT + 0] = a0;
                Weff[((size_t)l * F + f) * OUT + 1] = a1;
            }
        }
        __syncthreads();
        if (tid == 0) {
            __threadfence();
            atomicAdd(&g_weff_ready, 1);
        }
        return;
    }
    if (blockIdx.x == 128) {
        // ---- beff = b_fc + sum_j (b_pl+b_ll)[j] * W_fc[j,:] ----
        __shared__ float red0[256], red1[256];
        float a0 = 0.f, a1 = 0.f;
        for (int j = tid; j < L * H; j += 256) {
            float bb = b_pl[j] + b_ll[j];
            a0 += bb * W_fc[j * OUT + 0];
            a1 += bb * W_fc[j * OUT + 1];
        }
        red0[tid] = a0; red1[tid] = a1;
        __syncthreads();
        #pragma unroll
        for (int st = 128; st > 0; st >>= 1) {
            if (tid < st) { red0[tid] += red0[tid + st]; red1[tid] += red1[tid + st]; }
            __syncthreads();
        }
        if (tid == 0) {
            g_beff[0] = red0[0] + b_fc[0];
            g_beff[1] = red1[0] + b_fc[1];
            __threadfence();
            atomicAdd(&g_weff_ready, 1);
        }
        return;
    }

    // ================= aggregation blocks: merged two-relation pass =========
    __shared__ SmemAgg s;
    const int gb = blockIdx.x - WEFF_BLOCKS;
    const int l = gb / B;
    const int b = gb % B;

    const float* fp = feat_prot + ((size_t)l * N_PROT + b * NP) * F;
    const float* fl = feat_lig  + ((size_t)l * N_LIG  + b * NL) * F;

    const int* spl = src_pl + (size_t)l * B * E_PL_G + (size_t)b * E_PL_G;
    const int* dpl = dst_pl + (size_t)l * B * E_PL_G + (size_t)b * E_PL_G;
    const int* sll = src_ll + (size_t)l * B * E_LL_G + (size_t)b * E_LL_G;
    const int* dll = dst_ll + (size_t)l * B * E_LL_G + (size_t)b * E_LL_G;

    const int src_base_p = b * NP;
    const int dst_base   = b * NL;

    // ---- zero all counters ----
    for (int i = tid; i < NP; i += 256) s.cnt_src_p[i] = 0;
    if (tid < NL) {
        s.cnt_src_l[tid] = 0;
        s.cnt_dst_p[tid] = 0;
        s.cnt_dst_l[tid] = 0;
    }
    __syncthreads();

    // ---- single merged edge phase: all loads issued up front (streaming) ----
    {
        // PL: exactly one int4 per thread (256*4 = 1024 edges)
        int4 sv = __ldcs((const int4*)spl + tid);
        int4 dv = __ldcs((const int4*)dpl + tid);
        // LL: one int4 for threads < 64 (64*4 = 256 edges)
        int4 sv2, dv2;
        if (tid < 64) {
            sv2 = __ldcs((const int4*)sll + tid);
            dv2 = __ldcs((const int4*)dll + tid);
        }

        int sl0 = sv.x - src_base_p, sl1 = sv.y - src_base_p,
            sl2 = sv.z - src_base_p, sl3 = sv.w - src_base_p;
        int dl0 = dv.x - dst_base, dl1 = dv.y - dst_base,
            dl2 = dv.z - dst_base, dl3 = dv.w - dst_base;
        const int e = tid * 4;
        s.pack_pl[e + 0] = (unsigned short)((dl0 << 8) | sl0);
        s.pack_pl[e + 1] = (unsigned short)((dl1 << 8) | sl1);
        s.pack_pl[e + 2] = (unsigned short)((dl2 << 8) | sl2);
        s.pack_pl[e + 3] = (unsigned short)((dl3 << 8) | sl3);
        atomicAdd(&s.cnt_src_p[sl0], 1); atomicAdd(&s.cnt_src_p[sl1], 1);
        atomicAdd(&s.cnt_src_p[sl2], 1); atomicAdd(&s.cnt_src_p[sl3], 1);
        atomicAdd(&s.cnt_dst_p[dl0], 1); atomicAdd(&s.cnt_dst_p[dl1], 1);
        atomicAdd(&s.cnt_dst_p[dl2], 1); atomicAdd(&s.cnt_dst_p[dl3], 1);

        if (tid < 64) {
            int a0 = sv2.x - dst_base, a1 = sv2.y - dst_base,
                a2 = sv2.z - dst_base, a3 = sv2.w - dst_base;
            int c0 = dv2.x - dst_base, c1 = dv2.y - dst_base,
                c2 = dv2.z - dst_base, c3 = dv2.w - dst_base;
            s.pack_ll[e + 0] = (unsigned short)((c0 << 8) | a0);
            s.pack_ll[e + 1] = (unsigned short)((c1 << 8) | a1);
            s.pack_ll[e + 2] = (unsigned short)((c2 << 8) | a2);
            s.pack_ll[e + 3] = (unsigned short)((c3 << 8) | a3);
            atomicAdd(&s.cnt_src_l[a0], 1); atomicAdd(&s.cnt_src_l[a1], 1);
            atomicAdd(&s.cnt_src_l[a2], 1); atomicAdd(&s.cnt_src_l[a3], 1);
            atomicAdd(&s.cnt_dst_l[c0], 1); atomicAdd(&s.cnt_dst_l[c1], 1);
            atomicAdd(&s.cnt_dst_l[c2], 1); atomicAdd(&s.cnt_dst_l[c3], 1);
        }
    }
    __syncthreads();

    // ---- rs_dst (both relations) + zero coeffs ----
    if (tid < NL) {
        int cp = s.cnt_dst_p[tid], cl = s.cnt_dst_l[tid];
        s.rs_dst_p[tid] = rsqrtf((float)(cp > 0 ? cp : 1));
        s.rs_dst_l[tid] = rsqrtf((float)(cl > 0 ? cl : 1));
        s.coeff_l[tid]  = 0.f;
    }
    for (int i = tid; i < NP; i += 256) s.coeff_p[i] = 0.f;
    __syncthreads();

    // ---- coefficient accumulation (both relations in one round) ----
    {
        const int e = tid * 4;
        #pragma unroll
        for (int k = 0; k < 4; k++) {
            unsigned short p = s.pack_pl[e + k];
            atomicAdd(&s.coeff_p[p & 255], s.rs_dst_p[p >> 8]);
        }
        if (tid < E_LL_G) {
            unsigned short p = s.pack_ll[tid];
            atomicAdd(&s.coeff_l[p & 255], s.rs_dst_l[p >> 8]);
        }
    }
    __syncthreads();

    // ---- fold rs_src and 1/NL mean ----
    for (int i = tid; i < NP; i += 256) {
        int c = s.cnt_src_p[i];
        s.coeff_p[i] *= rsqrtf((float)(c > 0 ? c : 1)) * (1.0f / (float)NL);
    }
    if (tid < NL) {
        int c = s.cnt_src_l[tid];
        s.coeff_l[tid] *= rsqrtf((float)(c > 0 ? c : 1)) * (1.0f / (float)NL);
    }
    __syncthreads();

    // ---- single streaming phase: warp w owns 32 protein rows + 4 ligand rows
    // all feature loads use .cs (evict-first): every byte touched exactly once
    {
        float4 pp = make_float4(0.f, 0.f, 0.f, 0.f);
        float4 pl = make_float4(0.f, 0.f, 0.f, 0.f);
        const int rp0 = warp * 32;
        #pragma unroll 8
        for (int r = rp0; r < rp0 + 32; r++) {
            float c = s.coeff_p[r];
            float4 v = __ldcs((const float4*)(fp + (size_t)r * F) + lane);
            pp.x += c * v.x; pp.y += c * v.y; pp.z += c * v.z; pp.w += c * v.w;
        }
        const int rl0 = warp * 4;
        #pragma unroll
        for (int r = rl0; r < rl0 + 4; r++) {
            float c = s.coeff_l[r];
            float4 v = __ldcs((const float4*)(fl + (size_t)r * F) + lane);
            pl.x += c * v.x; pl.y += c * v.y; pl.z += c * v.z; pl.w += c * v.w;
        }
        ((float4*)(s.partial0 + warp * F))[lane] = pp;
        ((float4*)(s.partial1 + warp * F))[lane] = pl;
    }
    __syncthreads();

    // ---- wait for weff (done ~2us into the kernel; effectively free) ----
    if (tid == 0) {
        while (atomicCAS(&g_weff_ready, WEFF_TARGET, WEFF_TARGET) != WEFF_TARGET) {}
    }
    __syncthreads();

    // ---- reduce partials + dot with weff -> logit contribution ----
    float a0 = 0.f, a1 = 0.f;
    if (tid < F) {
        float p0 = 0.f, p1 = 0.f;
        #pragma unroll
        for (int w = 0; w < 8; w++) {
            p0 += s.partial0[w * F + tid];
            p1 += s.partial1[w * F + tid];
        }
        const int wi = (l * F + tid) * OUT;
        a0 = p0 * g_weff_pl[wi + 0] + p1 * g_weff_ll[wi + 0];
        a1 = p0 * g_weff_pl[wi + 1] + p1 * g_weff_ll[wi + 1];
    }
    #pragma unroll
    for (int o = 16; o > 0; o >>= 1) {
        a0 += __shfl_xor_sync(0xffffffffu, a0, o);
        a1 += __shfl_xor_sync(0xffffffffu, a1, o);
    }
    __shared__ float s0[8], s1[8];
    if (lane == 0) { s0[warp] = a0; s1[warp] = a1; }
    __syncthreads();

    if (tid == 0) {
        float t0 = s0[0] + s0[1] + s0[2] + s0[3];  // warps 4..7 had tid>=128 -> 0
        float t1 = s1[0] + s1[1] + s1[2] + s1[3];
        atomicAdd(&g_logit[b * OUT + 0], t0);
        atomicAdd(&g_logit[b * OUT + 1], t1);
        __threadfence();
        int old = atomicAdd(&g_cnt[b], 1);
        if (old == L - 1) {
            float v0 = atomicAdd(&g_logit[b * OUT + 0], 0.f) + g_beff[0];
            float v1 = atomicAdd(&g_logit[b * OUT + 1], 0.f) + g_beff[1];
            out[b * OUT + 0] = 1.0f / (1.0f + expf(-v0));
            out[b * OUT + 1] = 1.0f / (1.0f + expf(-v1));
            // restore zeros for the next replay
            g_logit[b * OUT + 0] = 0.f;
            g_logit[b * OUT + 1] = 0.f;
            g_cnt[b] = 0;
            __threadfence();
            int d = atomicAdd(&g_done, 1);
            if (d == B - 1) { g_done = 0; g_weff_ready = 0; __threadfence(); }
        }
    }
}

extern "C" void kernel_launch(void* const* d_in, const int* in_sizes, int n_in,
                              void* d_out, int out_size)
{
    const float* feat_lig  = (const float*)d_in[0];
    const float* feat_prot = (const float*)d_in[1];
    const int*   src_pl    = (const int*)  d_in[2];
    const int*   dst_pl    = (const int*)  d_in[3];
    const int*   src_ll    = (const int*)  d_in[4];
    const int*   dst_ll    = (const int*)  d_in[5];
    const float* W_pl      = (const float*)d_in[6];
    const float* b_pl      = (const float*)d_in[7];
    const float* W_ll      = (const float*)d_in[8];
    const float* b_ll      = (const float*)d_in[9];
    const float* W_fc      = (const float*)d_in[10];
    const float* b_fc      = (const float*)d_in[11];
    float* out = (float*)d_out;

    fused_kernel<<<WEFF_BLOCKS + AGG_BLOCKS, 256>>>(
        feat_lig, feat_prot, src_pl, dst_pl, src_ll, dst_ll,
        W_pl, W_ll, b_pl, b_ll, W_fc, b_fc, out);
}